// round 1
// baseline (speedup 1.0000x reference)
#include <cuda_runtime.h>
#include <math.h>

#define NN 50000
#define EE 500000
#define ESLN 550000   // EE + NN (edges with self loops)
#define FIN 128
#define HC 256
#define CH 128
#define NCLASS 10

// ---------------- scratch (static __device__ globals; no allocation) -------
__device__ int   g_src[ESLN];
__device__ int   g_dst[ESLN];
__device__ int   g_cnt[NN];
__device__ int   g_cursor[NN];
__device__ int   g_rowptr0[NN + 1];
__device__ int   g_rowptr1[NN + 1];
__device__ int   g_perm0[EE];
__device__ int   g_perm1[ESLN];
__device__ float g_XLR[(size_t)NN * 512];   // [N, 512]: cols 0..255 = xl, 256..511 = xr
__device__ float g_HA[(size_t)NN * HC];
__device__ float g_HB[(size_t)NN * HC];
__device__ float g_partial[256];
__device__ float g_wmean;

// ---------------- small utility kernels ------------------------------------
__global__ void zero_int_kernel(int* p, int n) {
    int i = blockIdx.x * blockDim.x + threadIdx.x;
    if (i < n) p[i] = 0;
}

// edge_index may be int32 or int64 depending on JAX x64 config.
// For int64 storage every odd 32-bit word (the high half) is 0 since values < 2^31.
__global__ void convert_edges_kernel(const unsigned int* __restrict__ ei,
                                     int* __restrict__ src, int* __restrict__ dst) {
    __shared__ int s_is64;
    if (threadIdx.x == 0) {
        unsigned int acc = 0;
#pragma unroll
        for (int k = 0; k < 32; k++) acc |= ei[2 * k + 1];
        s_is64 = (acc == 0u) ? 1 : 0;
    }
    __syncthreads();
    int is64 = s_is64;
    int i = blockIdx.x * blockDim.x + threadIdx.x;
    if (i >= ESLN) return;
    if (i < EE) {
        int s, d;
        if (is64) {
            const long long* p = reinterpret_cast<const long long*>(ei);
            s = (int)p[i];
            d = (int)p[EE + i];
        } else {
            const int* p = reinterpret_cast<const int*>(ei);
            s = p[i];
            d = p[EE + i];
        }
        src[i] = s;
        dst[i] = d;
    } else {
        int v = i - EE;  // self loop
        src[i] = v;
        dst[i] = v;
    }
}

__global__ void mean_partial_kernel(const float* __restrict__ w) {
    __shared__ float s[256];
    float acc = 0.f;
    for (int i = blockIdx.x * 256 + threadIdx.x; i < EE; i += 256 * 256) acc += w[i];
    s[threadIdx.x] = acc;
    __syncthreads();
    for (int off = 128; off > 0; off >>= 1) {
        if (threadIdx.x < off) s[threadIdx.x] += s[threadIdx.x + off];
        __syncthreads();
    }
    if (threadIdx.x == 0) g_partial[blockIdx.x] = s[0];
}

__global__ void mean_final_kernel() {
    __shared__ float s[256];
    s[threadIdx.x] = g_partial[threadIdx.x];
    __syncthreads();
    for (int off = 128; off > 0; off >>= 1) {
        if (threadIdx.x < off) s[threadIdx.x] += s[threadIdx.x + off];
        __syncthreads();
    }
    if (threadIdx.x == 0) g_wmean = s[0] / (float)EE;
}

__global__ void hist_kernel(const int* __restrict__ dst, int* __restrict__ cnt, int count) {
    int e = blockIdx.x * blockDim.x + threadIdx.x;
    if (e < count) atomicAdd(&cnt[dst[e]], 1);
}

// Single-block exclusive scan over NN counts; writes rowptr[0..NN] and cursor copy.
__global__ void scan_kernel(const int* __restrict__ cnt, int* __restrict__ rowptr,
                            int* __restrict__ cursor) {
    __shared__ int sdata[1024];
    __shared__ int s_carry;
    int t = threadIdx.x;
    if (t == 0) s_carry = 0;
    __syncthreads();
    for (int base = 0; base < NN; base += 1024) {
        int i = base + t;
        int v = (i < NN) ? cnt[i] : 0;
        sdata[t] = v;
        __syncthreads();
        for (int off = 1; off < 1024; off <<= 1) {
            int x = sdata[t];
            int y = (t >= off) ? sdata[t - off] : 0;
            __syncthreads();
            sdata[t] = x + y;
            __syncthreads();
        }
        int incl = sdata[t];
        int carry = s_carry;
        if (i < NN) {
            int ex = carry + incl - v;
            rowptr[i] = ex;
            cursor[i] = ex;
        }
        __syncthreads();
        if (t == 1023) s_carry = carry + incl;
        __syncthreads();
    }
    if (t == 0) rowptr[NN] = s_carry;
}

__global__ void scatter_kernel(const int* __restrict__ dst, int* __restrict__ cursor,
                               int* __restrict__ perm, int count) {
    int e = blockIdx.x * blockDim.x + threadIdx.x;
    if (e < count) {
        int p = atomicAdd(&cursor[dst[e]], 1);
        perm[p] = e;
    }
}

// ---------------- GEMM: C[N,512] = A[N,K] @ [Wl | Wr] + [bl | br] ----------
__global__ __launch_bounds__(256) void gemm_xlr_kernel(
    const float* __restrict__ A, int Mrows, int K,
    const float* __restrict__ Wl, const float* __restrict__ Wr,
    const float* __restrict__ bl, const float* __restrict__ br,
    float* __restrict__ Cmat) {
    __shared__ float As[16][132];
    __shared__ float Bs[16][132];
    const float* W = (blockIdx.y < 2) ? Wl : Wr;
    const float* bptr = (blockIdx.y < 2) ? bl : br;
    int colbase = (blockIdx.y & 1) * 128;
    int brow = blockIdx.x * 128;
    int tid = threadIdx.x;
    int tr = (tid >> 4) * 8;
    int tc = (tid & 15) * 8;
    float acc[8][8];
#pragma unroll
    for (int i = 0; i < 8; i++)
#pragma unroll
        for (int j = 0; j < 8; j++) acc[i][j] = 0.f;

    for (int kt = 0; kt < K; kt += 16) {
#pragma unroll
        for (int l = 0; l < 2; l++) {
            int id = tid + l * 256;
            int r = id >> 2;
            int c4 = (id & 3) * 4;
            int grow = brow + r;
            float4 v = make_float4(0.f, 0.f, 0.f, 0.f);
            if (grow < Mrows)
                v = *reinterpret_cast<const float4*>(A + (size_t)grow * K + kt + c4);
            As[c4 + 0][r] = v.x;
            As[c4 + 1][r] = v.y;
            As[c4 + 2][r] = v.z;
            As[c4 + 3][r] = v.w;
        }
#pragma unroll
        for (int l = 0; l < 2; l++) {
            int id = tid + l * 256;
            int r = id >> 5;
            int c4 = (id & 31) * 4;
            float4 v = *reinterpret_cast<const float4*>(W + (size_t)(kt + r) * HC + colbase + c4);
            *reinterpret_cast<float4*>(&Bs[r][c4]) = v;
        }
        __syncthreads();
#pragma unroll
        for (int k = 0; k < 16; k++) {
            float4 a0 = *reinterpret_cast<const float4*>(&As[k][tr]);
            float4 a1 = *reinterpret_cast<const float4*>(&As[k][tr + 4]);
            float4 b0 = *reinterpret_cast<const float4*>(&Bs[k][tc]);
            float4 b1 = *reinterpret_cast<const float4*>(&Bs[k][tc + 4]);
            float a[8] = {a0.x, a0.y, a0.z, a0.w, a1.x, a1.y, a1.z, a1.w};
            float b[8] = {b0.x, b0.y, b0.z, b0.w, b1.x, b1.y, b1.z, b1.w};
#pragma unroll
            for (int i = 0; i < 8; i++)
#pragma unroll
                for (int j = 0; j < 8; j++) acc[i][j] += a[i] * b[j];
        }
        __syncthreads();
    }
    float bias[8];
#pragma unroll
    for (int j = 0; j < 8; j++) bias[j] = bptr[colbase + tc + j];
    int gcol = blockIdx.y * 128 + tc;
#pragma unroll
    for (int i = 0; i < 8; i++) {
        int grow = brow + tr + i;
        if (grow < Mrows) {
            float4 v0, v1;
            v0.x = acc[i][0] + bias[0];
            v0.y = acc[i][1] + bias[1];
            v0.z = acc[i][2] + bias[2];
            v0.w = acc[i][3] + bias[3];
            v1.x = acc[i][4] + bias[4];
            v1.y = acc[i][5] + bias[5];
            v1.z = acc[i][6] + bias[6];
            v1.w = acc[i][7] + bias[7];
            *reinterpret_cast<float4*>(Cmat + (size_t)grow * 512 + gcol) = v0;
            *reinterpret_cast<float4*>(Cmat + (size_t)grow * 512 + gcol + 4) = v1;
        }
    }
}

// ---------------- fused GATv2 node kernel (online softmax) -----------------
// One warp per (node, head). Single pass over incident edges:
// logit -> running max/denominator -> weighted xl[src] accumulation.
// Epilogue: divide, add layer bias, ELU -> Hout.
__global__ __launch_bounds__(256) void gat_node_kernel(
    const float* __restrict__ XLR,
    const int* __restrict__ rowptr, const int* __restrict__ perm,
    const int* __restrict__ src, const float* __restrict__ wgt,
    const float* __restrict__ att, const float* __restrict__ We,
    const float* __restrict__ bias, float* __restrict__ Hout) {
    int wid = (blockIdx.x * blockDim.x + threadIdx.x) >> 5;
    if (wid >= NN * 2) return;
    int lane = threadIdx.x & 31;
    int node = wid >> 1;
    int h = wid & 1;
    int base = h * CH + lane * 4;
    const float4 xr = *reinterpret_cast<const float4*>(XLR + (size_t)node * 512 + 256 + base);
    const float4 av = *reinterpret_cast<const float4*>(att + base);
    const float4 wv = *reinterpret_cast<const float4*>(We + base);
    float m = -3.0e38f, d = 0.f;
    float4 acc = make_float4(0.f, 0.f, 0.f, 0.f);
    int i0 = rowptr[node], i1 = rowptr[node + 1];
    float wmean = g_wmean;
    for (int idx = i0; idx < i1; idx++) {
        int e = perm[idx];
        int s = src[e];
        float ea = (e < EE) ? __ldg(wgt + e) : wmean;
        float4 xl = *reinterpret_cast<const float4*>(XLR + (size_t)s * 512 + base);
        float t0 = xl.x + xr.x + ea * wv.x;
        float t1 = xl.y + xr.y + ea * wv.y;
        float t2 = xl.z + xr.z + ea * wv.z;
        float t3 = xl.w + xr.w + ea * wv.w;
        t0 = t0 > 0.f ? t0 : 0.2f * t0;
        t1 = t1 > 0.f ? t1 : 0.2f * t1;
        t2 = t2 > 0.f ? t2 : 0.2f * t2;
        t3 = t3 > 0.f ? t3 : 0.2f * t3;
        float p = t0 * av.x + t1 * av.y + t2 * av.z + t3 * av.w;
#pragma unroll
        for (int off = 16; off >= 1; off >>= 1) p += __shfl_xor_sync(0xffffffffu, p, off);
        float nm = fmaxf(m, p);
        float sc = expf(m - nm);   // 0 on first edge (m = -3e38)
        float pe = expf(p - nm);
        d = d * sc + pe;
        acc.x = acc.x * sc + pe * xl.x;
        acc.y = acc.y * sc + pe * xl.y;
        acc.z = acc.z * sc + pe * xl.z;
        acc.w = acc.w * sc + pe * xl.w;
        m = nm;
    }
    float inv = (i1 > i0) ? 1.f / (d + 1e-16f) : 0.f;
    const float4 bv = *reinterpret_cast<const float4*>(bias + base);
    float o0 = acc.x * inv + bv.x;
    float o1 = acc.y * inv + bv.y;
    float o2 = acc.z * inv + bv.z;
    float o3 = acc.w * inv + bv.w;
    // ELU (alpha=1)
    o0 = o0 > 0.f ? o0 : expm1f(o0);
    o1 = o1 > 0.f ? o1 : expm1f(o1);
    o2 = o2 > 0.f ? o2 : expm1f(o2);
    o3 = o3 > 0.f ? o3 : expm1f(o3);
    float4 outv = make_float4(o0, o1, o2, o3);
    *reinterpret_cast<float4*>(Hout + (size_t)node * HC + base) = outv;
}

// ---------------- final classifier ------------------------------------------
__global__ __launch_bounds__(256) void fc_kernel(const float* __restrict__ Hin,
                                                 const float* __restrict__ W,
                                                 const float* __restrict__ b,
                                                 float* __restrict__ out) {
    int wid = (blockIdx.x * blockDim.x + threadIdx.x) >> 5;
    if (wid >= NN) return;
    int lane = threadIdx.x & 31;
    float acc[NCLASS];
#pragma unroll
    for (int k = 0; k < NCLASS; k++) acc[k] = 0.f;
#pragma unroll
    for (int j0 = 0; j0 < HC; j0 += 32) {
        float hv = Hin[(size_t)wid * HC + j0 + lane];
        const float* wr = W + (size_t)(j0 + lane) * NCLASS;
#pragma unroll
        for (int k = 0; k < NCLASS; k++) acc[k] += hv * __ldg(wr + k);
    }
#pragma unroll
    for (int k = 0; k < NCLASS; k++) {
#pragma unroll
        for (int off = 16; off >= 1; off >>= 1)
            acc[k] += __shfl_xor_sync(0xffffffffu, acc[k], off);
    }
    if (lane == 0) {
#pragma unroll
        for (int k = 0; k < NCLASS; k++) out[(size_t)wid * NCLASS + k] = acc[k] + b[k];
    }
}

// ---------------- launch -----------------------------------------------------
extern "C" void kernel_launch(void* const* d_in, const int* in_sizes, int n_in,
                              void* d_out, int out_size) {
    const float* x = (const float*)d_in[0];
    const void* ei = d_in[1];
    const float* wgt = (const float*)d_in[2];
    const float *Wl[3], *bl[3], *Wr[3], *br[3], *We[3], *att[3], *bb[3];
    for (int i = 0; i < 3; i++) {
        int bse = 3 + 7 * i;
        Wl[i] = (const float*)d_in[bse + 0];
        bl[i] = (const float*)d_in[bse + 1];
        Wr[i] = (const float*)d_in[bse + 2];
        br[i] = (const float*)d_in[bse + 3];
        We[i] = (const float*)d_in[bse + 4];
        att[i] = (const float*)d_in[bse + 5];
        bb[i] = (const float*)d_in[bse + 6];
    }
    const float* fcW = (const float*)d_in[24];
    const float* fcb = (const float*)d_in[25];
    float* out = (float*)d_out;

    int *psrc, *pdst, *pcnt, *pcursor, *prow0, *prow1, *pperm0, *pperm1;
    float *pXLR, *pHA, *pHB;
    cudaGetSymbolAddress((void**)&psrc, g_src);
    cudaGetSymbolAddress((void**)&pdst, g_dst);
    cudaGetSymbolAddress((void**)&pcnt, g_cnt);
    cudaGetSymbolAddress((void**)&pcursor, g_cursor);
    cudaGetSymbolAddress((void**)&prow0, g_rowptr0);
    cudaGetSymbolAddress((void**)&prow1, g_rowptr1);
    cudaGetSymbolAddress((void**)&pperm0, g_perm0);
    cudaGetSymbolAddress((void**)&pperm1, g_perm1);
    cudaGetSymbolAddress((void**)&pXLR, g_XLR);
    cudaGetSymbolAddress((void**)&pHA, g_HA);
    cudaGetSymbolAddress((void**)&pHB, g_HB);

    // edge decode + self loops
    convert_edges_kernel<<<(ESLN + 255) / 256, 256>>>((const unsigned int*)ei, psrc, pdst);
    // mean of weight (for self-loop edge attr)
    mean_partial_kernel<<<256, 256>>>(wgt);
    mean_final_kernel<<<1, 256>>>();

    // CSR 0 (no self loops, layer 0)
    zero_int_kernel<<<(NN + 255) / 256, 256>>>(pcnt, NN);
    hist_kernel<<<(EE + 255) / 256, 256>>>(pdst, pcnt, EE);
    scan_kernel<<<1, 1024>>>(pcnt, prow0, pcursor);
    scatter_kernel<<<(EE + 255) / 256, 256>>>(pdst, pcursor, pperm0, EE);
    // CSR 1 (with self loops, layers 1-2)
    zero_int_kernel<<<(NN + 255) / 256, 256>>>(pcnt, NN);
    hist_kernel<<<(ESLN + 255) / 256, 256>>>(pdst, pcnt, ESLN);
    scan_kernel<<<1, 1024>>>(pcnt, prow1, pcursor);
    scatter_kernel<<<(ESLN + 255) / 256, 256>>>(pdst, pcursor, pperm1, ESLN);

    dim3 ggrid((NN + 127) / 128, 4);
    int node_blocks = (NN * 2 * 32 + 255) / 256;  // one warp per (node, head)

    // Layer 0
    gemm_xlr_kernel<<<ggrid, 256>>>(x, NN, FIN, Wl[0], Wr[0], bl[0], br[0], pXLR);
    gat_node_kernel<<<node_blocks, 256>>>(pXLR, prow0, pperm0, psrc, wgt,
                                          att[0], We[0], bb[0], pHA);
    // Layer 1
    gemm_xlr_kernel<<<ggrid, 256>>>(pHA, NN, HC, Wl[1], Wr[1], bl[1], br[1], pXLR);
    gat_node_kernel<<<node_blocks, 256>>>(pXLR, prow1, pperm1, psrc, wgt,
                                          att[1], We[1], bb[1], pHB);
    // Layer 2
    gemm_xlr_kernel<<<ggrid, 256>>>(pHB, NN, HC, Wl[2], Wr[2], bl[2], br[2], pXLR);
    gat_node_kernel<<<node_blocks, 256>>>(pXLR, prow1, pperm1, psrc, wgt,
                                          att[2], We[2], bb[2], pHA);
    // Classifier
    fc_kernel<<<(NN * 32 + 255) / 256, 256>>>(pHA, fcW, fcb, out);
}